// round 8
// baseline (speedup 1.0000x reference)
#include <cuda_runtime.h>
#include <cuda_bf16.h>

// Problem constants (shapes fixed by the dataset; runtime values read from in_sizes)
#define MAXN 100000
#define MAXE 1600000
#define HD   128           // hidden dim (= input dim)
#define NG   64            // number of graphs
#define BN_EPS 1e-5f

// NOTE: edge_index / batch are int32 on device (JAX default x64-disabled demotes the
// reference's jnp.int64 to int32). Reading them as int64 was the source of the
// err-719 aperture traps in earlier rounds.

// ---------------- scratch (static __device__ globals; no allocation) ----------------
__device__ __align__(256) float d_dinv[MAXN];              // rsqrt(in_deg + 1)
__device__ __align__(256) int   d_cntint[MAXN];            // in-degree counts
__device__ __align__(256) int   d_rowptr[MAXN + 1];        // CSR row pointers (by dst)
__device__ __align__(256) int   d_cursor[MAXN];            // fill cursors
__device__ __align__(256) int   d_col[MAXE];               // CSR column = src node
__device__ __align__(256) float d_h   [(size_t)MAXN * HD]; // transformed features
__device__ __align__(256) float d_agg [(size_t)MAXN * HD]; // aggregated features
__device__ __align__(256) float d_sum [2][HD];
__device__ __align__(256) float d_sq  [2][HD];
__device__ __align__(256) float d_aff_a[2][HD];            // BN scale : g * rsqrt(var+eps)
__device__ __align__(256) float d_aff_c[2][HD];            // BN shift : be - mu * scale
__device__ __align__(256) float d_pooled[NG * HD];
__device__ __align__(256) float d_cnt  [NG];

// ---------------- zeroing of accumulators (replayed each call) ----------------
__global__ void zero_kernel(int N) {
    int i = blockIdx.x * blockDim.x + threadIdx.x;
    int stride = gridDim.x * blockDim.x;
    for (int j = i; j < N; j += stride)       d_cntint[j] = 0;
    for (int j = i; j < NG * HD; j += stride) d_pooled[j] = 0.f;
    if (i < HD) {
        d_sum[0][i] = 0.f; d_sum[1][i] = 0.f;
        d_sq [0][i] = 0.f; d_sq [1][i] = 0.f;
    }
    if (i < NG) d_cnt[i] = 0.f;
}

// ---------------- in-degree counting (by dst) ----------------
__global__ void deg_kernel(const int* __restrict__ ei, int E) {
    int e = blockIdx.x * blockDim.x + threadIdx.x;
    if (e < E) atomicAdd(&d_cntint[ei[E + e]], 1);
}

// ---------------- single-block exclusive scan -> rowptr, cursor, dinv --------------
__global__ __launch_bounds__(1024) void scan_kernel(int N) {
    __shared__ int partial[1024];
    int t = threadIdx.x;
    int C = (N + 1023) / 1024;
    int lo = t * C, hi = min(lo + C, N);
    int s = 0;
    for (int j = lo; j < hi; j++) s += d_cntint[j];
    partial[t] = s;
    __syncthreads();
    // inclusive block scan (Hillis-Steele in shared)
    for (int off = 1; off < 1024; off <<= 1) {
        int v = (t >= off) ? partial[t - off] : 0;
        __syncthreads();
        partial[t] += v;
        __syncthreads();
    }
    int run = (t == 0) ? 0 : partial[t - 1];   // exclusive base for this chunk
    for (int j = lo; j < hi; j++) {
        int c = d_cntint[j];
        d_rowptr[j] = run;
        d_cursor[j] = run;
        d_dinv[j]   = rsqrtf((float)c + 1.0f);  // +1 self loop
        run += c;
    }
    if (t == 1023) d_rowptr[N] = run;
}

// ---------------- CSR fill: col[pos] = src, bucketed by dst ----------------
__global__ void fill_kernel(const int* __restrict__ ei, int E) {
    int e = blockIdx.x * blockDim.x + threadIdx.x;
    if (e >= E) return;
    int s = ei[e];
    int d = ei[E + e];
    int pos = atomicAdd(&d_cursor[d], 1);
    d_col[pos] = s;
}

// ---------------- GEMM: d_h = A @ W ----------------
// AFF=true: A is d_agg(prev layer) with BN+ReLU applied on-the-fly to each element.
template <bool AFF>
__global__ __launch_bounds__(256) void gemm_kernel(const float* __restrict__ Aexp,
                                                   const float* __restrict__ W, int M) {
    __shared__ float As[8][128];
    __shared__ float Bs[8][128];
    const float* A = AFF ? (const float*)d_agg : Aexp;

    int t   = threadIdx.x;
    int br  = blockIdx.x;
    int rowA = t >> 1;            // 0..127  (A-tile loader row)
    int part = t & 1;             // which half of the 8-wide K chunk
    int kw   = t >> 5;            // 0..7    (W-tile loader k)
    int nw   = (t & 31) << 2;     // 0..124  (W-tile loader col*4)
    int ty = t >> 4, tx = t & 15;
    int m0 = ty * 8, n0 = tx * 8;

    float acc[8][8];
#pragma unroll
    for (int i = 0; i < 8; i++)
#pragma unroll
        for (int j = 0; j < 8; j++) acc[i][j] = 0.f;

    long grow = (long)br * 128 + rowA;
    bool rvalid = grow < M;

    for (int kc = 0; kc < 128; kc += 8) {
        float4 av = make_float4(0.f, 0.f, 0.f, 0.f);
        if (rvalid) av = *(const float4*)(A + grow * 128 + kc + part * 4);
        if (AFF) {
            float4 aa = *(const float4*)(&d_aff_a[0][kc + part * 4]);
            float4 cc = *(const float4*)(&d_aff_c[0][kc + part * 4]);
            av.x = fmaxf(fmaf(av.x, aa.x, cc.x), 0.f);
            av.y = fmaxf(fmaf(av.y, aa.y, cc.y), 0.f);
            av.z = fmaxf(fmaf(av.z, aa.z, cc.z), 0.f);
            av.w = fmaxf(fmaf(av.w, aa.w, cc.w), 0.f);
            if (!rvalid) { av.x = av.y = av.z = av.w = 0.f; }
        }
        float4 bv = *(const float4*)(W + (long)(kc + kw) * 128 + nw);

        __syncthreads();
        As[part * 4 + 0][rowA] = av.x;
        As[part * 4 + 1][rowA] = av.y;
        As[part * 4 + 2][rowA] = av.z;
        As[part * 4 + 3][rowA] = av.w;
        *(float4*)&Bs[kw][nw] = bv;
        __syncthreads();

#pragma unroll
        for (int k = 0; k < 8; k++) {
            float4 a0 = *(const float4*)&As[k][m0];
            float4 a1 = *(const float4*)&As[k][m0 + 4];
            float4 b0 = *(const float4*)&Bs[k][n0];
            float4 b1 = *(const float4*)&Bs[k][n0 + 4];
            float am[8] = {a0.x, a0.y, a0.z, a0.w, a1.x, a1.y, a1.z, a1.w};
            float bn[8] = {b0.x, b0.y, b0.z, b0.w, b1.x, b1.y, b1.z, b1.w};
#pragma unroll
            for (int i = 0; i < 8; i++)
#pragma unroll
                for (int j = 0; j < 8; j++) acc[i][j] = fmaf(am[i], bn[j], acc[i][j]);
        }
    }

#pragma unroll
    for (int i = 0; i < 8; i++) {
        long r = (long)br * 128 + m0 + i;
        if (r < M) {
            *(float4*)(d_h + r * 128 + n0)     = make_float4(acc[i][0], acc[i][1], acc[i][2], acc[i][3]);
            *(float4*)(d_h + r * 128 + n0 + 4) = make_float4(acc[i][4], acc[i][5], acc[i][6], acc[i][7]);
        }
    }
}

// ---------------- gather-aggregate: warp per node, no float atomics ----------------
// agg[d] = dinv[d] * ( sum_{src in N(d)} dinv[src] * h[src] ) + dinv[d]^2 * h[d]
__global__ __launch_bounds__(256) void aggregate_kernel(int N) {
    int warp_id = (blockIdx.x * blockDim.x + threadIdx.x) >> 5;
    int lane    = threadIdx.x & 31;
    int nwarps  = (gridDim.x * blockDim.x) >> 5;

    for (int n = warp_id; n < N; n += nwarps) {
        int beg = d_rowptr[n];
        int end = d_rowptr[n + 1];
        float4 acc = make_float4(0.f, 0.f, 0.f, 0.f);

        for (int j0 = beg; j0 < end; j0 += 32) {
            int cnt = min(32, end - j0);
            int  myidx  = (lane < cnt) ? d_col[j0 + lane] : 0;     // coalesced
            float mynrm = (lane < cnt) ? d_dinv[myidx] : 0.f;
#pragma unroll 4
            for (int k = 0; k < cnt; k++) {
                int   s = __shfl_sync(0xffffffffu, myidx, k);
                float w = __shfl_sync(0xffffffffu, mynrm, k);
                float4 v = *(const float4*)(d_h + (long)s * 128 + lane * 4);
                acc.x = fmaf(w, v.x, acc.x);
                acc.y = fmaf(w, v.y, acc.y);
                acc.z = fmaf(w, v.z, acc.z);
                acc.w = fmaf(w, v.w, acc.w);
            }
        }

        float di = d_dinv[n];
        float4 hv = *(const float4*)(d_h + (long)n * 128 + lane * 4);
        float4 o;
        o.x = di * (acc.x + di * hv.x);
        o.y = di * (acc.y + di * hv.y);
        o.z = di * (acc.z + di * hv.z);
        o.w = di * (acc.w + di * hv.w);
        *(float4*)(d_agg + (long)n * 128 + lane * 4) = o;
    }
}

// ---------------- per-column sum / sumsq over d_agg ----------------
template <int L>
__global__ void stats_kernel(int N) {
    int c = threadIdx.x;   // 128 threads, one column each
    float s = 0.f, q = 0.f;
    for (int r = blockIdx.x; r < N; r += gridDim.x) {
        float v = d_agg[(long)r * 128 + c];
        s += v; q += v * v;
    }
    atomicAdd(&d_sum[L][c], s);
    atomicAdd(&d_sq [L][c], q);
}

template <int L>
__global__ void finalize_kernel(const float* __restrict__ g, const float* __restrict__ be,
                                int N) {
    int c = threadIdx.x;
    float invN = 1.0f / (float)N;
    float mu  = d_sum[L][c] * invN;
    float var = d_sq[L][c] * invN - mu * mu;
    float a   = g[c] * rsqrtf(var + BN_EPS);
    d_aff_a[L][c] = a;
    d_aff_c[L][c] = be[c] - mu * a;
}

// ---------------- pooling (batch sorted): per-block running segment sums -----------
__global__ void pool_kernel(const int* __restrict__ batch, int N) {
    int c = threadIdx.x;     // 128 threads, one column each
    int B = gridDim.x;
    int chunk = (N + B - 1) / B;
    int r0 = blockIdx.x * chunk;
    int r1 = min(r0 + chunk, N);
    if (r0 >= r1) return;
    float a  = d_aff_a[1][c];
    float cc = d_aff_c[1][c];
    int curg = batch[r0];
    float acc = 0.f, cnt = 0.f;
    for (int r = r0; r < r1; r++) {
        int g = batch[r];
        if (g != curg) {
            atomicAdd(&d_pooled[curg * HD + c], acc);
            if (c == 0) atomicAdd(&d_cnt[curg], cnt);
            acc = 0.f; cnt = 0.f; curg = g;
        }
        float v = d_agg[(long)r * 128 + c];
        acc += fmaxf(fmaf(v, a, cc), 0.f);
        cnt += 1.f;
    }
    atomicAdd(&d_pooled[curg * HD + c], acc);
    if (c == 0) atomicAdd(&d_cnt[curg], cnt);
}

// ---------------- final FC: out[g][o] = (pooled[g]/cnt[g]) @ Wfc + bfc -------------
__global__ void fc_kernel(const float* __restrict__ Wfc, const float* __restrict__ bfc,
                          float* __restrict__ out, int O) {
    int t = blockIdx.x * blockDim.x + threadIdx.x;
    int g = t / O;
    int o = t % O;
    if (g >= NG) return;
    float inv = 1.0f / fmaxf(d_cnt[g], 1.0f);
    float s = bfc[o];
#pragma unroll 8
    for (int c = 0; c < HD; c++)
        s = fmaf(d_pooled[g * HD + c] * inv, Wfc[c * O + o], s);
    out[g * O + o] = s;
}

// =====================================================================================
extern "C" void kernel_launch(void* const* d_in, const int* in_sizes, int n_in,
                              void* d_out, int out_size) {
    const float* x     = (const float*)d_in[0];
    const int*   ei    = (const int*)d_in[1];     // int32 (see note at top)
    const int*   batch = (const int*)d_in[2];     // int32
    const float* W0    = (const float*)d_in[3];
    // d_in[4] = b0 : cancels inside BatchNorm -> unused
    const float* g0    = (const float*)d_in[5];
    const float* be0   = (const float*)d_in[6];
    const float* W1    = (const float*)d_in[7];
    // d_in[8] = b1 : cancels inside BatchNorm -> unused
    const float* g1    = (const float*)d_in[9];
    const float* be1   = (const float*)d_in[10];
    const float* Wfc   = (const float*)d_in[11];
    const float* bfc   = (const float*)d_in[12];
    float*       out   = (float*)d_out;

    int N = in_sizes[0] / HD;        // 100000
    int E = in_sizes[1] / 2;         // 1600000
    int O = out_size / NG;           // 32

    cudaStream_t st = 0;

    // 0) zero accumulators, build CSR (by dst) + dinv
    zero_kernel<<<(N + 255) / 256, 256, 0, st>>>(N);
    deg_kernel <<<(E + 255) / 256, 256, 0, st>>>(ei, E);
    scan_kernel<<<1, 1024, 0, st>>>(N);
    fill_kernel<<<(E + 255) / 256, 256, 0, st>>>(ei, E);

    int gemm_grid = (N + 127) / 128;
    int agg_grid  = 2048;            // 256 thr = 8 warps each -> 16384 warps

    // ---- layer 1 ----
    gemm_kernel<false><<<gemm_grid, 256, 0, st>>>(x, W0, N);
    aggregate_kernel  <<<agg_grid, 256, 0, st>>>(N);
    stats_kernel<0>   <<<1024, 128, 0, st>>>(N);
    finalize_kernel<0><<<1, 128, 0, st>>>(g0, be0, N);

    // ---- layer 2 (BN+ReLU of layer 1 fused into the GEMM A-load) ----
    gemm_kernel<true> <<<gemm_grid, 256, 0, st>>>(x /*unused*/, W1, N);
    aggregate_kernel  <<<agg_grid, 256, 0, st>>>(N);
    stats_kernel<1>   <<<1024, 128, 0, st>>>(N);
    finalize_kernel<1><<<1, 128, 0, st>>>(g1, be1, N);

    // ---- pooling (BN+ReLU of layer 2 fused) + FC ----
    pool_kernel<<<512, 128, 0, st>>>(batch, N);
    fc_kernel  <<<(NG * O + 255) / 256, 256, 0, st>>>(Wfc, bfc, out, O);
}

// round 9
// speedup vs baseline: 1.4983x; 1.4983x over previous
#include <cuda_runtime.h>
#include <cuda_bf16.h>

// Problem constants (shapes fixed by the dataset; runtime values read from in_sizes)
#define MAXN 100000
#define MAXE 1600000
#define HD   128           // hidden dim (= input dim)
#define NG   64            // number of graphs
#define BN_EPS 1e-5f

// edge_index / batch are int32 on device (JAX x64-disabled demotes jnp.int64).

// ---------------- scratch (static __device__ globals; no allocation) ----------------
__device__ __align__(256) float d_dinv[MAXN];              // rsqrt(in_deg + 1)
__device__ __align__(256) int   d_cntint[MAXN];            // in-degree counts
__device__ __align__(256) int   d_rowptr[MAXN + 1];        // CSR row pointers (by dst)
__device__ __align__(256) int   d_cursor[MAXN];            // fill cursors
__device__ __align__(256) int   d_col[MAXE];               // CSR column = src node
__device__ __align__(256) float d_h   [(size_t)MAXN * HD]; // transformed features
__device__ __align__(256) float d_agg [(size_t)MAXN * HD]; // aggregated features
__device__ __align__(256) float d_sum [2][HD];
__device__ __align__(256) float d_sq  [2][HD];
__device__ __align__(256) float d_aff_a[2][HD];            // BN scale : g * rsqrt(var+eps)
__device__ __align__(256) float d_aff_c[2][HD];            // BN shift : be - mu * scale
__device__ __align__(256) float d_pooled[NG * HD];
__device__ __align__(256) float d_cnt  [NG];

// ---------------- zeroing of accumulators (replayed each call) ----------------
__global__ void zero_kernel(int N) {
    int i = blockIdx.x * blockDim.x + threadIdx.x;
    int stride = gridDim.x * blockDim.x;
    for (int j = i; j < N; j += stride)       d_cntint[j] = 0;
    for (int j = i; j < NG * HD; j += stride) d_pooled[j] = 0.f;
    if (i < HD) {
        d_sum[0][i] = 0.f; d_sum[1][i] = 0.f;
        d_sq [0][i] = 0.f; d_sq [1][i] = 0.f;
    }
    if (i < NG) d_cnt[i] = 0.f;
}

// ---------------- in-degree counting (by dst) ----------------
__global__ void deg_kernel(const int* __restrict__ ei, int E) {
    int e = blockIdx.x * blockDim.x + threadIdx.x;
    if (e < E) atomicAdd(&d_cntint[ei[E + e]], 1);
}

// ---------------- single-block exclusive scan -> rowptr, cursor, dinv --------------
__global__ __launch_bounds__(1024) void scan_kernel(int N) {
    __shared__ int partial[1024];
    int t = threadIdx.x;
    int C = (N + 1023) / 1024;
    int lo = t * C, hi = min(lo + C, N);
    int s = 0;
    for (int j = lo; j < hi; j++) s += d_cntint[j];
    partial[t] = s;
    __syncthreads();
    for (int off = 1; off < 1024; off <<= 1) {
        int v = (t >= off) ? partial[t - off] : 0;
        __syncthreads();
        partial[t] += v;
        __syncthreads();
    }
    int run = (t == 0) ? 0 : partial[t - 1];
    for (int j = lo; j < hi; j++) {
        int c = d_cntint[j];
        d_rowptr[j] = run;
        d_cursor[j] = run;
        d_dinv[j]   = rsqrtf((float)c + 1.0f);  // +1 self loop
        run += c;
    }
    if (t == 1023) d_rowptr[N] = run;
}

// ---------------- CSR fill: col[pos] = src, bucketed by dst ----------------
__global__ void fill_kernel(const int* __restrict__ ei, int E) {
    int e = blockIdx.x * blockDim.x + threadIdx.x;
    if (e >= E) return;
    int s = ei[e];
    int d = ei[E + e];
    int pos = atomicAdd(&d_cursor[d], 1);
    d_col[pos] = s;
}

// ---------------- GEMM: d_h = A @ W ----------------
// AFF=true: A is d_agg(prev layer) with BN+ReLU applied on-the-fly to each element.
template <bool AFF>
__global__ __launch_bounds__(256) void gemm_kernel(const float* __restrict__ Aexp,
                                                   const float* __restrict__ W, int M) {
    __shared__ float As[8][128];
    __shared__ float Bs[8][128];
    const float* A = AFF ? (const float*)d_agg : Aexp;

    int t   = threadIdx.x;
    int br  = blockIdx.x;
    int rowA = t >> 1;
    int part = t & 1;
    int kw   = t >> 5;
    int nw   = (t & 31) << 2;
    int ty = t >> 4, tx = t & 15;
    int m0 = ty * 8, n0 = tx * 8;

    float acc[8][8];
#pragma unroll
    for (int i = 0; i < 8; i++)
#pragma unroll
        for (int j = 0; j < 8; j++) acc[i][j] = 0.f;

    long grow = (long)br * 128 + rowA;
    bool rvalid = grow < M;

    for (int kc = 0; kc < 128; kc += 8) {
        float4 av = make_float4(0.f, 0.f, 0.f, 0.f);
        if (rvalid) av = *(const float4*)(A + grow * 128 + kc + part * 4);
        if (AFF) {
            float4 aa = *(const float4*)(&d_aff_a[0][kc + part * 4]);
            float4 cc = *(const float4*)(&d_aff_c[0][kc + part * 4]);
            av.x = fmaxf(fmaf(av.x, aa.x, cc.x), 0.f);
            av.y = fmaxf(fmaf(av.y, aa.y, cc.y), 0.f);
            av.z = fmaxf(fmaf(av.z, aa.z, cc.z), 0.f);
            av.w = fmaxf(fmaf(av.w, aa.w, cc.w), 0.f);
            if (!rvalid) { av.x = av.y = av.z = av.w = 0.f; }
        }
        float4 bv = *(const float4*)(W + (long)(kc + kw) * 128 + nw);

        __syncthreads();
        As[part * 4 + 0][rowA] = av.x;
        As[part * 4 + 1][rowA] = av.y;
        As[part * 4 + 2][rowA] = av.z;
        As[part * 4 + 3][rowA] = av.w;
        *(float4*)&Bs[kw][nw] = bv;
        __syncthreads();

#pragma unroll
        for (int k = 0; k < 8; k++) {
            float4 a0 = *(const float4*)&As[k][m0];
            float4 a1 = *(const float4*)&As[k][m0 + 4];
            float4 b0 = *(const float4*)&Bs[k][n0];
            float4 b1 = *(const float4*)&Bs[k][n0 + 4];
            float am[8] = {a0.x, a0.y, a0.z, a0.w, a1.x, a1.y, a1.z, a1.w};
            float bn[8] = {b0.x, b0.y, b0.z, b0.w, b1.x, b1.y, b1.z, b1.w};
#pragma unroll
            for (int i = 0; i < 8; i++)
#pragma unroll
                for (int j = 0; j < 8; j++) acc[i][j] = fmaf(am[i], bn[j], acc[i][j]);
        }
    }

#pragma unroll
    for (int i = 0; i < 8; i++) {
        long r = (long)br * 128 + m0 + i;
        if (r < M) {
            *(float4*)(d_h + r * 128 + n0)     = make_float4(acc[i][0], acc[i][1], acc[i][2], acc[i][3]);
            *(float4*)(d_h + r * 128 + n0 + 4) = make_float4(acc[i][4], acc[i][5], acc[i][6], acc[i][7]);
        }
    }
}

// ---------------- gather-aggregate + fused BN stats ----------------
// agg[d] = dinv[d]*( sum_{src in N(d)} dinv[src]*h[src] ) + dinv[d]^2*h[d]
// Also accumulates per-column sum / sumsq of agg into d_sum[L]/d_sq[L].
// 8-deep explicit load batching: 8 independent LDG.128 in flight per warp.
template <int L>
__global__ __launch_bounds__(256) void aggregate_kernel(int N) {
    __shared__ float bsum[HD];
    __shared__ float bsq [HD];
    int t = threadIdx.x;
    if (t < HD) { bsum[t] = 0.f; bsq[t] = 0.f; }
    __syncthreads();

    int warp_id = (blockIdx.x * blockDim.x + t) >> 5;
    int lane    = t & 31;
    int nwarps  = (gridDim.x * blockDim.x) >> 5;

    float4 s4 = make_float4(0.f, 0.f, 0.f, 0.f);   // column sums (this lane's 4 cols)
    float4 q4 = make_float4(0.f, 0.f, 0.f, 0.f);   // column sumsq

    for (int n = warp_id; n < N; n += nwarps) {
        int beg = d_rowptr[n];
        int end = d_rowptr[n + 1];
        float4 acc = make_float4(0.f, 0.f, 0.f, 0.f);

        for (int j0 = beg; j0 < end; j0 += 32) {
            int cnt = min(32, end - j0);
            int  myidx  = (lane < cnt) ? d_col[j0 + lane] : 0;     // coalesced
            float mynrm = (lane < cnt) ? d_dinv[myidx] : 0.f;
            int k = 0;
            for (; k + 8 <= cnt; k += 8) {
                int   si[8]; float wi[8]; float4 v[8];
#pragma unroll
                for (int u = 0; u < 8; u++) {
                    si[u] = __shfl_sync(0xffffffffu, myidx, k + u);
                    wi[u] = __shfl_sync(0xffffffffu, mynrm, k + u);
                }
#pragma unroll
                for (int u = 0; u < 8; u++)
                    v[u] = *(const float4*)(d_h + (long)si[u] * 128 + lane * 4);
#pragma unroll
                for (int u = 0; u < 8; u++) {
                    acc.x = fmaf(wi[u], v[u].x, acc.x);
                    acc.y = fmaf(wi[u], v[u].y, acc.y);
                    acc.z = fmaf(wi[u], v[u].z, acc.z);
                    acc.w = fmaf(wi[u], v[u].w, acc.w);
                }
            }
            for (; k < cnt; k++) {
                int   s = __shfl_sync(0xffffffffu, myidx, k);
                float w = __shfl_sync(0xffffffffu, mynrm, k);
                float4 v = *(const float4*)(d_h + (long)s * 128 + lane * 4);
                acc.x = fmaf(w, v.x, acc.x);
                acc.y = fmaf(w, v.y, acc.y);
                acc.z = fmaf(w, v.z, acc.z);
                acc.w = fmaf(w, v.w, acc.w);
            }
        }

        float di = d_dinv[n];
        float4 hv = *(const float4*)(d_h + (long)n * 128 + lane * 4);
        float4 o;
        o.x = di * (acc.x + di * hv.x);
        o.y = di * (acc.y + di * hv.y);
        o.z = di * (acc.z + di * hv.z);
        o.w = di * (acc.w + di * hv.w);
        *(float4*)(d_agg + (long)n * 128 + lane * 4) = o;

        s4.x += o.x; s4.y += o.y; s4.z += o.z; s4.w += o.w;
        q4.x = fmaf(o.x, o.x, q4.x);
        q4.y = fmaf(o.y, o.y, q4.y);
        q4.z = fmaf(o.z, o.z, q4.z);
        q4.w = fmaf(o.w, o.w, q4.w);
    }

    // block-level column reduction (8 warps contend per smem address: cheap)
    int c0 = lane * 4;
    atomicAdd(&bsum[c0 + 0], s4.x); atomicAdd(&bsq[c0 + 0], q4.x);
    atomicAdd(&bsum[c0 + 1], s4.y); atomicAdd(&bsq[c0 + 1], q4.y);
    atomicAdd(&bsum[c0 + 2], s4.z); atomicAdd(&bsq[c0 + 2], q4.z);
    atomicAdd(&bsum[c0 + 3], s4.w); atomicAdd(&bsq[c0 + 3], q4.w);
    __syncthreads();
    if (t < HD) {
        atomicAdd(&d_sum[L][t], bsum[t]);
        atomicAdd(&d_sq [L][t], bsq [t]);
    }
}

template <int L>
__global__ void finalize_kernel(const float* __restrict__ g, const float* __restrict__ be,
                                int N) {
    int c = threadIdx.x;
    float invN = 1.0f / (float)N;
    float mu  = d_sum[L][c] * invN;
    float var = d_sq[L][c] * invN - mu * mu;
    float a   = g[c] * rsqrtf(var + BN_EPS);
    d_aff_a[L][c] = a;
    d_aff_c[L][c] = be[c] - mu * a;
}

// ---------------- pooling (batch sorted): per-block running segment sums -----------
__global__ void pool_kernel(const int* __restrict__ batch, int N) {
    int c = threadIdx.x;     // 128 threads, one column each
    int B = gridDim.x;
    int chunk = (N + B - 1) / B;
    int r0 = blockIdx.x * chunk;
    int r1 = min(r0 + chunk, N);
    if (r0 >= r1) return;
    float a  = d_aff_a[1][c];
    float cc = d_aff_c[1][c];
    int curg = batch[r0];
    float acc = 0.f, cnt = 0.f;
    for (int r = r0; r < r1; r++) {
        int g = batch[r];
        if (g != curg) {
            atomicAdd(&d_pooled[curg * HD + c], acc);
            if (c == 0) atomicAdd(&d_cnt[curg], cnt);
            acc = 0.f; cnt = 0.f; curg = g;
        }
        float v = d_agg[(long)r * 128 + c];
        acc += fmaxf(fmaf(v, a, cc), 0.f);
        cnt += 1.f;
    }
    atomicAdd(&d_pooled[curg * HD + c], acc);
    if (c == 0) atomicAdd(&d_cnt[curg], cnt);
}

// ---------------- final FC: out[g][o] = (pooled[g]/cnt[g]) @ Wfc + bfc -------------
__global__ void fc_kernel(const float* __restrict__ Wfc, const float* __restrict__ bfc,
                          float* __restrict__ out, int O) {
    int t = blockIdx.x * blockDim.x + threadIdx.x;
    int g = t / O;
    int o = t % O;
    if (g >= NG) return;
    float inv = 1.0f / fmaxf(d_cnt[g], 1.0f);
    float s = bfc[o];
#pragma unroll 8
    for (int c = 0; c < HD; c++)
        s = fmaf(d_pooled[g * HD + c] * inv, Wfc[c * O + o], s);
    out[g * O + o] = s;
}

// =====================================================================================
extern "C" void kernel_launch(void* const* d_in, const int* in_sizes, int n_in,
                              void* d_out, int out_size) {
    const float* x     = (const float*)d_in[0];
    const int*   ei    = (const int*)d_in[1];     // int32
    const int*   batch = (const int*)d_in[2];     // int32
    const float* W0    = (const float*)d_in[3];
    // d_in[4] = b0 : cancels inside BatchNorm -> unused
    const float* g0    = (const float*)d_in[5];
    const float* be0   = (const float*)d_in[6];
    const float* W1    = (const float*)d_in[7];
    // d_in[8] = b1 : cancels inside BatchNorm -> unused
    const float* g1    = (const float*)d_in[9];
    const float* be1   = (const float*)d_in[10];
    const float* Wfc   = (const float*)d_in[11];
    const float* bfc   = (const float*)d_in[12];
    float*       out   = (float*)d_out;

    int N = in_sizes[0] / HD;        // 100000
    int E = in_sizes[1] / 2;         // 1600000
    int O = out_size / NG;           // 32

    cudaStream_t st = 0;

    // 0) zero accumulators, build CSR (by dst) + dinv
    zero_kernel<<<(N + 255) / 256, 256, 0, st>>>(N);
    deg_kernel <<<(E + 255) / 256, 256, 0, st>>>(ei, E);
    scan_kernel<<<1, 1024, 0, st>>>(N);
    fill_kernel<<<(E + 255) / 256, 256, 0, st>>>(ei, E);

    int gemm_grid = (N + 127) / 128;
    int agg_grid  = 4096;            // 8 warps/block -> 32768 warps, ~3 nodes each

    // ---- layer 1 ----
    gemm_kernel<false><<<gemm_grid, 256, 0, st>>>(x, W0, N);
    aggregate_kernel<0><<<agg_grid, 256, 0, st>>>(N);
    finalize_kernel<0><<<1, 128, 0, st>>>(g0, be0, N);

    // ---- layer 2 (BN+ReLU of layer 1 fused into the GEMM A-load) ----
    gemm_kernel<true> <<<gemm_grid, 256, 0, st>>>(x /*unused*/, W1, N);
    aggregate_kernel<1><<<agg_grid, 256, 0, st>>>(N);
    finalize_kernel<1><<<1, 128, 0, st>>>(g1, be1, N);

    // ---- pooling (BN+ReLU of layer 2 fused) + FC ----
    pool_kernel<<<512, 128, 0, st>>>(batch, N);
    fc_kernel  <<<(NG * O + 255) / 256, 256, 0, st>>>(Wfc, bfc, out, O);
}

// round 11
// speedup vs baseline: 1.5108x; 1.0083x over previous
#include <cuda_runtime.h>
#include <cuda_bf16.h>

// Problem constants (shapes fixed by the dataset; runtime values read from in_sizes)
#define MAXN 100000
#define MAXE 1600000
#define HD   128           // hidden dim (= input dim)
#define NG   64            // number of graphs
#define BN_EPS 1e-5f

// edge_index / batch are int32 on device (JAX x64-disabled demotes jnp.int64).

// ---------------- scratch (static __device__ globals; no allocation) ----------------
__device__ __align__(256) float d_dinv[MAXN];              // rsqrt(in_deg + 1)
__device__ __align__(256) int   d_cntint[MAXN];            // in-degree counts
__device__ __align__(256) int   d_rowptr[MAXN + 1];        // CSR row pointers (by dst)
__device__ __align__(256) int   d_cursor[MAXN];            // fill cursors
__device__ __align__(256) int   d_col[MAXE];               // CSR column = src node
__device__ __align__(256) float d_h   [(size_t)MAXN * HD]; // transformed features
__device__ __align__(256) float d_agg [(size_t)MAXN * HD]; // aggregated features
__device__ __align__(256) float d_sum [2][HD];
__device__ __align__(256) float d_sq  [2][HD];
__device__ __align__(256) float d_aff_a[2][HD];            // BN scale : g * rsqrt(var+eps)
__device__ __align__(256) float d_aff_c[2][HD];            // BN shift : be - mu * scale
__device__ __align__(256) float d_pooled[NG * HD];
__device__ __align__(256) float d_cnt  [NG];

// ---------------- packed f32x2 helpers (FFMA2: 2 fp32 FMA per issue slot) -----------
__device__ __forceinline__ unsigned long long pack2(float lo, float hi) {
    unsigned long long r;
    asm("mov.b64 %0, {%1,%2};" : "=l"(r) : "f"(lo), "f"(hi));
    return r;
}
__device__ __forceinline__ void unpack2(unsigned long long v, float& lo, float& hi) {
    asm("mov.b64 {%0,%1}, %2;" : "=f"(lo), "=f"(hi) : "l"(v));
}
__device__ __forceinline__ unsigned long long ffma2(unsigned long long a,
                                                    unsigned long long b,
                                                    unsigned long long c) {
    unsigned long long r;
    asm("fma.rn.f32x2 %0, %1, %2, %3;" : "=l"(r) : "l"(a), "l"(b), "l"(c));
    return r;
}

// ---------------- zeroing of accumulators (replayed each call) ----------------
__global__ void zero_kernel(int N) {
    int i = blockIdx.x * blockDim.x + threadIdx.x;
    int stride = gridDim.x * blockDim.x;
    for (int j = i; j < N; j += stride)       d_cntint[j] = 0;
    for (int j = i; j < NG * HD; j += stride) d_pooled[j] = 0.f;
    if (i < HD) {
        d_sum[0][i] = 0.f; d_sum[1][i] = 0.f;
        d_sq [0][i] = 0.f; d_sq [1][i] = 0.f;
    }
    if (i < NG) d_cnt[i] = 0.f;
}

// ---------------- in-degree counting (by dst) ----------------
__global__ void deg_kernel(const int* __restrict__ ei, int E) {
    int e = blockIdx.x * blockDim.x + threadIdx.x;
    if (e < E) atomicAdd(&d_cntint[ei[E + e]], 1);
}

// ---------------- single-block exclusive scan -> rowptr, cursor, dinv --------------
__global__ __launch_bounds__(1024) void scan_kernel(int N) {
    __shared__ int partial[1024];
    int t = threadIdx.x;
    int C = (N + 1023) / 1024;
    int lo = t * C, hi = min(lo + C, N);
    int s = 0;
    for (int j = lo; j < hi; j++) s += d_cntint[j];
    partial[t] = s;
    __syncthreads();
    for (int off = 1; off < 1024; off <<= 1) {
        int v = (t >= off) ? partial[t - off] : 0;
        __syncthreads();
        partial[t] += v;
        __syncthreads();
    }
    int run = (t == 0) ? 0 : partial[t - 1];
    for (int j = lo; j < hi; j++) {
        int c = d_cntint[j];
        d_rowptr[j] = run;
        d_cursor[j] = run;
        d_dinv[j]   = rsqrtf((float)c + 1.0f);  // +1 self loop
        run += c;
    }
    if (t == 1023) d_rowptr[N] = run;
}

// ---------------- CSR fill: col[pos] = src, bucketed by dst ----------------
__global__ void fill_kernel(const int* __restrict__ ei, int E) {
    int e = blockIdx.x * blockDim.x + threadIdx.x;
    if (e >= E) return;
    int s = ei[e];
    int d = ei[E + e];
    int pos = atomicAdd(&d_cursor[d], 1);
    d_col[pos] = s;
}

// ---------------- GEMM: d_h = A @ W  (packed f32x2 FMA inner loop) ----------------
// Accumulators packed along M: acc2[ip][j] holds rows (m0+2ip, m0+2ip+1) of column n0+j.
// A-operand pairs load directly from shared as b64 (no packing cost); B duplicated.
// AFF=true: A is d_agg(prev layer) with BN+ReLU applied on-the-fly to each element.
template <bool AFF>
__global__ __launch_bounds__(256) void gemm_kernel(const float* __restrict__ Aexp,
                                                   const float* __restrict__ W, int M) {
    __shared__ float As[8][128];
    __shared__ float Bs[8][128];
    const float* A = AFF ? (const float*)d_agg : Aexp;

    int t   = threadIdx.x;
    int br  = blockIdx.x;
    int rowA = t >> 1;
    int part = t & 1;
    int kw   = t >> 5;
    int nw   = (t & 31) << 2;
    int ty = t >> 4, tx = t & 15;
    int m0 = ty * 8, n0 = tx * 8;

    unsigned long long acc2[4][8];
#pragma unroll
    for (int ip = 0; ip < 4; ip++)
#pragma unroll
        for (int j = 0; j < 8; j++) acc2[ip][j] = 0ull;

    long grow = (long)br * 128 + rowA;
    bool rvalid = grow < M;

    for (int kc = 0; kc < 128; kc += 8) {
        float4 av = make_float4(0.f, 0.f, 0.f, 0.f);
        if (rvalid) av = *(const float4*)(A + grow * 128 + kc + part * 4);
        if (AFF) {
            float4 aa = *(const float4*)(&d_aff_a[0][kc + part * 4]);
            float4 cc = *(const float4*)(&d_aff_c[0][kc + part * 4]);
            av.x = fmaxf(fmaf(av.x, aa.x, cc.x), 0.f);
            av.y = fmaxf(fmaf(av.y, aa.y, cc.y), 0.f);
            av.z = fmaxf(fmaf(av.z, aa.z, cc.z), 0.f);
            av.w = fmaxf(fmaf(av.w, aa.w, cc.w), 0.f);
            if (!rvalid) { av.x = av.y = av.z = av.w = 0.f; }
        }
        float4 bv = *(const float4*)(W + (long)(kc + kw) * 128 + nw);

        __syncthreads();
        As[part * 4 + 0][rowA] = av.x;
        As[part * 4 + 1][rowA] = av.y;
        As[part * 4 + 2][rowA] = av.z;
        As[part * 4 + 3][rowA] = av.w;
        *(float4*)&Bs[kw][nw] = bv;
        __syncthreads();

#pragma unroll
        for (int k = 0; k < 8; k++) {
            // A pairs directly from shared (16B-aligned): (m0,m0+1)...(m0+6,m0+7)
            const ulonglong2* ap = (const ulonglong2*)&As[k][m0];
            ulonglong2 Alo = ap[0];
            ulonglong2 Ahi = ap[1];
            unsigned long long am2[4] = {Alo.x, Alo.y, Ahi.x, Ahi.y};

            float4 b0 = *(const float4*)&Bs[k][n0];
            float4 b1 = *(const float4*)&Bs[k][n0 + 4];
            unsigned long long bd[8];
            bd[0] = pack2(b0.x, b0.x); bd[1] = pack2(b0.y, b0.y);
            bd[2] = pack2(b0.z, b0.z); bd[3] = pack2(b0.w, b0.w);
            bd[4] = pack2(b1.x, b1.x); bd[5] = pack2(b1.y, b1.y);
            bd[6] = pack2(b1.z, b1.z); bd[7] = pack2(b1.w, b1.w);

#pragma unroll
            for (int ip = 0; ip < 4; ip++)
#pragma unroll
                for (int j = 0; j < 8; j++)
                    acc2[ip][j] = ffma2(am2[ip], bd[j], acc2[ip][j]);
        }
    }

#pragma unroll
    for (int ip = 0; ip < 4; ip++) {
        float vlo[8], vhi[8];
#pragma unroll
        for (int j = 0; j < 8; j++) unpack2(acc2[ip][j], vlo[j], vhi[j]);
        long r0 = (long)br * 128 + m0 + ip * 2;
        if (r0 < M) {
            *(float4*)(d_h + r0 * 128 + n0)     = make_float4(vlo[0], vlo[1], vlo[2], vlo[3]);
            *(float4*)(d_h + r0 * 128 + n0 + 4) = make_float4(vlo[4], vlo[5], vlo[6], vlo[7]);
        }
        if (r0 + 1 < M) {
            *(float4*)(d_h + (r0 + 1) * 128 + n0)     = make_float4(vhi[0], vhi[1], vhi[2], vhi[3]);
            *(float4*)(d_h + (r0 + 1) * 128 + n0 + 4) = make_float4(vhi[4], vhi[5], vhi[6], vhi[7]);
        }
    }
}

// ---------------- gather-aggregate + fused BN stats ----------------
// agg[d] = dinv[d]*( sum_{src in N(d)} dinv[src]*h[src] ) + dinv[d]^2*h[d]
// Also accumulates per-column sum / sumsq of agg into d_sum[L]/d_sq[L].
// 8-deep explicit load batching: 8 independent LDG.128 in flight per warp.
template <int L>
__global__ __launch_bounds__(256) void aggregate_kernel(int N) {
    __shared__ float bsum[HD];
    __shared__ float bsq [HD];
    int t = threadIdx.x;
    if (t < HD) { bsum[t] = 0.f; bsq[t] = 0.f; }
    __syncthreads();

    int warp_id = (blockIdx.x * blockDim.x + t) >> 5;
    int lane    = t & 31;
    int nwarps  = (gridDim.x * blockDim.x) >> 5;

    float4 s4 = make_float4(0.f, 0.f, 0.f, 0.f);
    float4 q4 = make_float4(0.f, 0.f, 0.f, 0.f);

    for (int n = warp_id; n < N; n += nwarps) {
        int beg = d_rowptr[n];
        int end = d_rowptr[n + 1];
        float4 acc = make_float4(0.f, 0.f, 0.f, 0.f);

        for (int j0 = beg; j0 < end; j0 += 32) {
            int cnt = min(32, end - j0);
            int  myidx  = (lane < cnt) ? d_col[j0 + lane] : 0;     // coalesced
            float mynrm = (lane < cnt) ? d_dinv[myidx] : 0.f;
            int k = 0;
            for (; k + 8 <= cnt; k += 8) {
                int   si[8]; float wi[8]; float4 v[8];
#pragma unroll
                for (int u = 0; u < 8; u++) {
                    si[u] = __shfl_sync(0xffffffffu, myidx, k + u);
                    wi[u] = __shfl_sync(0xffffffffu, mynrm, k + u);
                }
#pragma unroll
                for (int u = 0; u < 8; u++)
                    v[u] = *(const float4*)(d_h + (long)si[u] * 128 + lane * 4);
#pragma unroll
                for (int u = 0; u < 8; u++) {
                    acc.x = fmaf(wi[u], v[u].x, acc.x);
                    acc.y = fmaf(wi[u], v[u].y, acc.y);
                    acc.z = fmaf(wi[u], v[u].z, acc.z);
                    acc.w = fmaf(wi[u], v[u].w, acc.w);
                }
            }
            for (; k < cnt; k++) {
                int   s = __shfl_sync(0xffffffffu, myidx, k);
                float w = __shfl_sync(0xffffffffu, mynrm, k);
                float4 v = *(const float4*)(d_h + (long)s * 128 + lane * 4);
                acc.x = fmaf(w, v.x, acc.x);
                acc.y = fmaf(w, v.y, acc.y);
                acc.z = fmaf(w, v.z, acc.z);
                acc.w = fmaf(w, v.w, acc.w);
            }
        }

        float di = d_dinv[n];
        float4 hv = *(const float4*)(d_h + (long)n * 128 + lane * 4);
        float4 o;
        o.x = di * (acc.x + di * hv.x);
        o.y = di * (acc.y + di * hv.y);
        o.z = di * (acc.z + di * hv.z);
        o.w = di * (acc.w + di * hv.w);
        *(float4*)(d_agg + (long)n * 128 + lane * 4) = o;

        s4.x += o.x; s4.y += o.y; s4.z += o.z; s4.w += o.w;
        q4.x = fmaf(o.x, o.x, q4.x);
        q4.y = fmaf(o.y, o.y, q4.y);
        q4.z = fmaf(o.z, o.z, q4.z);
        q4.w = fmaf(o.w, o.w, q4.w);
    }

    int c0 = lane * 4;
    atomicAdd(&bsum[c0 + 0], s4.x); atomicAdd(&bsq[c0 + 0], q4.x);
    atomicAdd(&bsum[c0 + 1], s4.y); atomicAdd(&bsq[c0 + 1], q4.y);
    atomicAdd(&bsum[c0 + 2], s4.z); atomicAdd(&bsq[c0 + 2], q4.z);
    atomicAdd(&bsum[c0 + 3], s4.w); atomicAdd(&bsq[c0 + 3], q4.w);
    __syncthreads();
    if (t < HD) {
        atomicAdd(&d_sum[L][t], bsum[t]);
        atomicAdd(&d_sq [L][t], bsq [t]);
    }
}

template <int L>
__global__ void finalize_kernel(const float* __restrict__ g, const float* __restrict__ be,
                                int N) {
    int c = threadIdx.x;
    float invN = 1.0f / (float)N;
    float mu  = d_sum[L][c] * invN;
    float var = d_sq[L][c] * invN - mu * mu;
    float a   = g[c] * rsqrtf(var + BN_EPS);
    d_aff_a[L][c] = a;
    d_aff_c[L][c] = be[c] - mu * a;
}

// ---------------- pooling (batch sorted): per-block running segment sums -----------
__global__ void pool_kernel(const int* __restrict__ batch, int N) {
    int c = threadIdx.x;     // 128 threads, one column each
    int B = gridDim.x;
    int chunk = (N + B - 1) / B;
    int r0 = blockIdx.x * chunk;
    int r1 = min(r0 + chunk, N);
    if (r0 >= r1) return;
    float a  = d_aff_a[1][c];
    float cc = d_aff_c[1][c];
    int curg = batch[r0];
    float acc = 0.f, cnt = 0.f;
    for (int r = r0; r < r1; r++) {
        int g = batch[r];
        if (g != curg) {
            atomicAdd(&d_pooled[curg * HD + c], acc);
            if (c == 0) atomicAdd(&d_cnt[curg], cnt);
            acc = 0.f; cnt = 0.f; curg = g;
        }
        float v = d_agg[(long)r * 128 + c];
        acc += fmaxf(fmaf(v, a, cc), 0.f);
        cnt += 1.f;
    }
    atomicAdd(&d_pooled[curg * HD + c], acc);
    if (c == 0) atomicAdd(&d_cnt[curg], cnt);
}

// ---------------- final FC: out[g][o] = (pooled[g]/cnt[g]) @ Wfc + bfc -------------
__global__ void fc_kernel(const float* __restrict__ Wfc, const float* __restrict__ bfc,
                          float* __restrict__ out, int O) {
    int t = blockIdx.x * blockDim.x + threadIdx.x;
    int g = t / O;
    int o = t % O;
    if (g >= NG) return;
    float inv = 1.0f / fmaxf(d_cnt[g], 1.0f);
    float s = bfc[o];
#pragma unroll 8
    for (int c = 0; c < HD; c++)
        s = fmaf(d_pooled[g * HD + c] * inv, Wfc[c * O + o], s);
    out[g * O + o] = s;
}

// =====================================================================================
extern "C" void kernel_launch(void* const* d_in, const int* in_sizes, int n_in,
                              void* d_out, int out_size) {
    const float* x     = (const float*)d_in[0];
    const int*   ei    = (const int*)d_in[1];     // int32
    const int*   batch = (const int*)d_in[2];     // int32
    const float* W0    = (const float*)d_in[3];
    // d_in[4] = b0 : cancels inside BatchNorm -> unused
    const float* g0    = (const float*)d_in[5];
    const float* be0   = (const float*)d_in[6];
    const float* W1    = (const float*)d_in[7];
    // d_in[8] = b1 : cancels inside BatchNorm -> unused
    const float* g1    = (const float*)d_in[9];
    const float* be1   = (const float*)d_in[10];
    const float* Wfc   = (const float*)d_in[11];
    const float* bfc   = (const float*)d_in[12];
    float*       out   = (float*)d_out;

    int N = in_sizes[0] / HD;        // 100000
    int E = in_sizes[1] / 2;         // 1600000
    int O = out_size / NG;           // 32

    cudaStream_t st = 0;

    // 0) zero accumulators, build CSR (by dst) + dinv
    zero_kernel<<<(N + 255) / 256, 256, 0, st>>>(N);
    deg_kernel <<<(E + 255) / 256, 256, 0, st>>>(ei, E);
    scan_kernel<<<1, 1024, 0, st>>>(N);
    fill_kernel<<<(E + 255) / 256, 256, 0, st>>>(ei, E);

    int gemm_grid = (N + 127) / 128;
    int agg_grid  = 4096;            // 8 warps/block -> 32768 warps

    // ---- layer 1 ----
    gemm_kernel<false><<<gemm_grid, 256, 0, st>>>(x, W0, N);
    aggregate_kernel<0><<<agg_grid, 256, 0, st>>>(N);
    finalize_kernel<0><<<1, 128, 0, st>>>(g0, be0, N);

    // ---- layer 2 (BN+ReLU of layer 1 fused into the GEMM A-load) ----
    gemm_kernel<true> <<<gemm_grid, 256, 0, st>>>(x /*unused*/, W1, N);
    aggregate_kernel<1><<<agg_grid, 256, 0, st>>>(N);
    finalize_kernel<1><<<1, 128, 0, st>>>(g1, be1, N);

    // ---- pooling (BN+ReLU of layer 2 fused) + FC ----
    pool_kernel<<<512, 128, 0, st>>>(batch, N);
    fc_kernel  <<<(NG * O + 255) / 256, 256, 0, st>>>(Wfc, bfc, out, O);
}

// round 13
// speedup vs baseline: 1.5697x; 1.0389x over previous
#include <cuda_runtime.h>
#include <cuda_bf16.h>

// Problem constants (shapes fixed by the dataset; runtime values read from in_sizes)
#define MAXN 100000
#define MAXE 1600000
#define HD   128           // hidden dim (= input dim)
#define NG   64            // number of graphs
#define BN_EPS 1e-5f

// edge_index / batch are int32 on device (JAX x64-disabled demotes jnp.int64).

// ---------------- scratch (static __device__ globals; no allocation) ----------------
__device__ __align__(256) float d_dinv[MAXN];              // rsqrt(in_deg + 1)
__device__ __align__(256) int   d_cntint[MAXN];            // in-degree counts
__device__ __align__(256) int   d_rowptr[MAXN + 1];        // CSR row pointers (by dst)
__device__ __align__(256) int   d_cursor[MAXN];            // fill cursors
__device__ __align__(256) int   d_col[MAXE];               // CSR column = src node
__device__ __align__(256) float d_h   [(size_t)MAXN * HD]; // transformed features
__device__ __align__(256) float d_agg [(size_t)MAXN * HD]; // aggregated features
__device__ __align__(256) float d_sum [2][HD];
__device__ __align__(256) float d_sq  [2][HD];
__device__ __align__(256) float d_aff_a[2][HD];            // BN scale : g * rsqrt(var+eps)
__device__ __align__(256) float d_aff_c[2][HD];            // BN shift : be - mu * scale
__device__ __align__(256) float d_pooled[NG * HD];
__device__ __align__(256) float d_cnt  [NG];

// ---------------- packed f32x2 helpers ----------------
__device__ __forceinline__ unsigned long long pack2(float lo, float hi) {
    unsigned long long r;
    asm("mov.b64 %0, {%1,%2};" : "=l"(r) : "f"(lo), "f"(hi));
    return r;
}
__device__ __forceinline__ void unpack2(unsigned long long v, float& lo, float& hi) {
    asm("mov.b64 {%0,%1}, %2;" : "=f"(lo), "=f"(hi) : "l"(v));
}
__device__ __forceinline__ unsigned long long ffma2(unsigned long long a,
                                                    unsigned long long b,
                                                    unsigned long long c) {
    unsigned long long r;
    asm("fma.rn.f32x2 %0, %1, %2, %3;" : "=l"(r) : "l"(a), "l"(b), "l"(c));
    return r;
}

// ---------------- zeroing of accumulators (replayed each call) ----------------
__global__ void zero_kernel(int N) {
    int i = blockIdx.x * blockDim.x + threadIdx.x;
    int stride = gridDim.x * blockDim.x;
    for (int j = i; j < N; j += stride)       d_cntint[j] = 0;
    for (int j = i; j < NG * HD; j += stride) d_pooled[j] = 0.f;
    if (i < HD) {
        d_sum[0][i] = 0.f; d_sum[1][i] = 0.f;
        d_sq [0][i] = 0.f; d_sq [1][i] = 0.f;
    }
    if (i < NG) d_cnt[i] = 0.f;
}

// ---------------- in-degree counting (by dst) ----------------
__global__ void deg_kernel(const int* __restrict__ ei, int E) {
    int e = blockIdx.x * blockDim.x + threadIdx.x;
    if (e < E) atomicAdd(&d_cntint[ei[E + e]], 1);
}

// ---------------- single-block exclusive scan -> rowptr, cursor, dinv --------------
__global__ __launch_bounds__(1024) void scan_kernel(int N) {
    __shared__ int partial[1024];
    int t = threadIdx.x;
    int C = (N + 1023) / 1024;
    int lo = t * C, hi = min(lo + C, N);
    int s = 0;
    for (int j = lo; j < hi; j++) s += d_cntint[j];
    partial[t] = s;
    __syncthreads();
    for (int off = 1; off < 1024; off <<= 1) {
        int v = (t >= off) ? partial[t - off] : 0;
        __syncthreads();
        partial[t] += v;
        __syncthreads();
    }
    int run = (t == 0) ? 0 : partial[t - 1];
    for (int j = lo; j < hi; j++) {
        int c = d_cntint[j];
        d_rowptr[j] = run;
        d_cursor[j] = run;
        d_dinv[j]   = rsqrtf((float)c + 1.0f);  // +1 self loop
        run += c;
    }
    if (t == 1023) d_rowptr[N] = run;
}

// ---------------- CSR fill: col[pos] = src, bucketed by dst ----------------
__global__ void fill_kernel(const int* __restrict__ ei, int E) {
    int e = blockIdx.x * blockDim.x + threadIdx.x;
    if (e >= E) return;
    int s = ei[e];
    int d = ei[E + e];
    int pos = atomicAdd(&d_cursor[d], 1);
    d_col[pos] = s;
}

// ---------------- GEMM: d_h = A @ W  (packed f32x2 FMA inner loop) ----------------
template <bool AFF>
__global__ __launch_bounds__(256) void gemm_kernel(const float* __restrict__ Aexp,
                                                   const float* __restrict__ W, int M) {
    __shared__ float As[8][128];
    __shared__ float Bs[8][128];
    const float* A = AFF ? (const float*)d_agg : Aexp;

    int t   = threadIdx.x;
    int br  = blockIdx.x;
    int rowA = t >> 1;
    int part = t & 1;
    int kw   = t >> 5;
    int nw   = (t & 31) << 2;
    int ty = t >> 4, tx = t & 15;
    int m0 = ty * 8, n0 = tx * 8;

    unsigned long long acc2[4][8];
#pragma unroll
    for (int ip = 0; ip < 4; ip++)
#pragma unroll
        for (int j = 0; j < 8; j++) acc2[ip][j] = 0ull;

    long grow = (long)br * 128 + rowA;
    bool rvalid = grow < M;

    for (int kc = 0; kc < 128; kc += 8) {
        float4 av = make_float4(0.f, 0.f, 0.f, 0.f);
        if (rvalid) av = *(const float4*)(A + grow * 128 + kc + part * 4);
        if (AFF) {
            float4 aa = *(const float4*)(&d_aff_a[0][kc + part * 4]);
            float4 cc = *(const float4*)(&d_aff_c[0][kc + part * 4]);
            av.x = fmaxf(fmaf(av.x, aa.x, cc.x), 0.f);
            av.y = fmaxf(fmaf(av.y, aa.y, cc.y), 0.f);
            av.z = fmaxf(fmaf(av.z, aa.z, cc.z), 0.f);
            av.w = fmaxf(fmaf(av.w, aa.w, cc.w), 0.f);
            if (!rvalid) { av.x = av.y = av.z = av.w = 0.f; }
        }
        float4 bv = *(const float4*)(W + (long)(kc + kw) * 128 + nw);

        __syncthreads();
        As[part * 4 + 0][rowA] = av.x;
        As[part * 4 + 1][rowA] = av.y;
        As[part * 4 + 2][rowA] = av.z;
        As[part * 4 + 3][rowA] = av.w;
        *(float4*)&Bs[kw][nw] = bv;
        __syncthreads();

#pragma unroll
        for (int k = 0; k < 8; k++) {
            const ulonglong2* ap = (const ulonglong2*)&As[k][m0];
            ulonglong2 Alo = ap[0];
            ulonglong2 Ahi = ap[1];
            unsigned long long am2[4] = {Alo.x, Alo.y, Ahi.x, Ahi.y};

            float4 b0 = *(const float4*)&Bs[k][n0];
            float4 b1 = *(const float4*)&Bs[k][n0 + 4];
            unsigned long long bd[8];
            bd[0] = pack2(b0.x, b0.x); bd[1] = pack2(b0.y, b0.y);
            bd[2] = pack2(b0.z, b0.z); bd[3] = pack2(b0.w, b0.w);
            bd[4] = pack2(b1.x, b1.x); bd[5] = pack2(b1.y, b1.y);
            bd[6] = pack2(b1.z, b1.z); bd[7] = pack2(b1.w, b1.w);

#pragma unroll
            for (int ip = 0; ip < 4; ip++)
#pragma unroll
                for (int j = 0; j < 8; j++)
                    acc2[ip][j] = ffma2(am2[ip], bd[j], acc2[ip][j]);
        }
    }

#pragma unroll
    for (int ip = 0; ip < 4; ip++) {
        float vlo[8], vhi[8];
#pragma unroll
        for (int j = 0; j < 8; j++) unpack2(acc2[ip][j], vlo[j], vhi[j]);
        long r0 = (long)br * 128 + m0 + ip * 2;
        if (r0 < M) {
            *(float4*)(d_h + r0 * 128 + n0)     = make_float4(vlo[0], vlo[1], vlo[2], vlo[3]);
            *(float4*)(d_h + r0 * 128 + n0 + 4) = make_float4(vlo[4], vlo[5], vlo[6], vlo[7]);
        }
        if (r0 + 1 < M) {
            *(float4*)(d_h + (r0 + 1) * 128 + n0)     = make_float4(vhi[0], vhi[1], vhi[2], vhi[3]);
            *(float4*)(d_h + (r0 + 1) * 128 + n0 + 4) = make_float4(vhi[4], vhi[5], vhi[6], vhi[7]);
        }
    }
}

// ---------------- gather-aggregate + fused BN stats ----------------
// Fully-batched predicated edge loop: ALWAYS 8 independent LDG.128 in flight;
// lanes past cnt get clamped (valid) indices with weight 0 — no serial tail.
template <int L>
__global__ __launch_bounds__(256) void aggregate_kernel(int N) {
    __shared__ float bsum[HD];
    __shared__ float bsq [HD];
    int t = threadIdx.x;
    if (t < HD) { bsum[t] = 0.f; bsq[t] = 0.f; }
    __syncthreads();

    int warp_id = (blockIdx.x * blockDim.x + t) >> 5;
    int lane    = t & 31;
    int nwarps  = (gridDim.x * blockDim.x) >> 5;

    float4 s4 = make_float4(0.f, 0.f, 0.f, 0.f);
    float4 q4 = make_float4(0.f, 0.f, 0.f, 0.f);

    for (int n = warp_id; n < N; n += nwarps) {
        int beg = d_rowptr[n];
        int end = d_rowptr[n + 1];
        float4 acc = make_float4(0.f, 0.f, 0.f, 0.f);

        for (int j0 = beg; j0 < end; j0 += 32) {
            int cnt = min(32, end - j0);
            int  myidx  = d_col[j0 + min(lane, cnt - 1)];          // clamped, coalesced
            float mynrm = (lane < cnt) ? d_dinv[myidx] : 0.f;      // OOB lanes weight 0

            for (int k = 0; k < cnt; k += 8) {                     // <=4 iters, each fully batched
                int si[8]; float wi[8]; float4 v[8];
#pragma unroll
                for (int u = 0; u < 8; u++) {
                    si[u] = __shfl_sync(0xffffffffu, myidx, k + u);
                    wi[u] = __shfl_sync(0xffffffffu, mynrm, k + u);
                }
#pragma unroll
                for (int u = 0; u < 8; u++)
                    v[u] = *(const float4*)(d_h + (long)si[u] * 128 + lane * 4);
#pragma unroll
                for (int u = 0; u < 8; u++) {
                    acc.x = fmaf(wi[u], v[u].x, acc.x);
                    acc.y = fmaf(wi[u], v[u].y, acc.y);
                    acc.z = fmaf(wi[u], v[u].z, acc.z);
                    acc.w = fmaf(wi[u], v[u].w, acc.w);
                }
            }
        }

        float di = d_dinv[n];
        float4 hv = *(const float4*)(d_h + (long)n * 128 + lane * 4);
        float4 o;
        o.x = di * (acc.x + di * hv.x);
        o.y = di * (acc.y + di * hv.y);
        o.z = di * (acc.z + di * hv.z);
        o.w = di * (acc.w + di * hv.w);
        *(float4*)(d_agg + (long)n * 128 + lane * 4) = o;

        s4.x += o.x; s4.y += o.y; s4.z += o.z; s4.w += o.w;
        q4.x = fmaf(o.x, o.x, q4.x);
        q4.y = fmaf(o.y, o.y, q4.y);
        q4.z = fmaf(o.z, o.z, q4.z);
        q4.w = fmaf(o.w, o.w, q4.w);
    }

    int c0 = lane * 4;
    atomicAdd(&bsum[c0 + 0], s4.x); atomicAdd(&bsq[c0 + 0], q4.x);
    atomicAdd(&bsum[c0 + 1], s4.y); atomicAdd(&bsq[c0 + 1], q4.y);
    atomicAdd(&bsum[c0 + 2], s4.z); atomicAdd(&bsq[c0 + 2], q4.z);
    atomicAdd(&bsum[c0 + 3], s4.w); atomicAdd(&bsq[c0 + 3], q4.w);
    __syncthreads();
    if (t < HD) {
        atomicAdd(&d_sum[L][t], bsum[t]);
        atomicAdd(&d_sq [L][t], bsq [t]);
    }
}

template <int L>
__global__ void finalize_kernel(const float* __restrict__ g, const float* __restrict__ be,
                                int N) {
    int c = threadIdx.x;
    float invN = 1.0f / (float)N;
    float mu  = d_sum[L][c] * invN;
    float var = d_sq[L][c] * invN - mu * mu;
    float a   = g[c] * rsqrtf(var + BN_EPS);
    d_aff_a[L][c] = a;
    d_aff_c[L][c] = be[c] - mu * a;
}

// ---------------- pooling (batch sorted): per-block running segment sums -----------
__global__ void pool_kernel(const int* __restrict__ batch, int N) {
    int c = threadIdx.x;
    int B = gridDim.x;
    int chunk = (N + B - 1) / B;
    int r0 = blockIdx.x * chunk;
    int r1 = min(r0 + chunk, N);
    if (r0 >= r1) return;
    float a  = d_aff_a[1][c];
    float cc = d_aff_c[1][c];
    int curg = batch[r0];
    float acc = 0.f, cnt = 0.f;
    for (int r = r0; r < r1; r++) {
        int g = batch[r];
        if (g != curg) {
            atomicAdd(&d_pooled[curg * HD + c], acc);
            if (c == 0) atomicAdd(&d_cnt[curg], cnt);
            acc = 0.f; cnt = 0.f; curg = g;
        }
        float v = d_agg[(long)r * 128 + c];
        acc += fmaxf(fmaf(v, a, cc), 0.f);
        cnt += 1.f;
    }
    atomicAdd(&d_pooled[curg * HD + c], acc);
    if (c == 0) atomicAdd(&d_cnt[curg], cnt);
}

// ---------------- final FC: out[g][o] = (pooled[g]/cnt[g]) @ Wfc + bfc -------------
__global__ void fc_kernel(const float* __restrict__ Wfc, const float* __restrict__ bfc,
                          float* __restrict__ out, int O) {
    int t = blockIdx.x * blockDim.x + threadIdx.x;
    int g = t / O;
    int o = t % O;
    if (g >= NG) return;
    float inv = 1.0f / fmaxf(d_cnt[g], 1.0f);
    float s = bfc[o];
#pragma unroll 8
    for (int c = 0; c < HD; c++)
        s = fmaf(d_pooled[g * HD + c] * inv, Wfc[c * O + o], s);
    out[g * O + o] = s;
}

// =====================================================================================
extern "C" void kernel_launch(void* const* d_in, const int* in_sizes, int n_in,
                              void* d_out, int out_size) {
    const float* x     = (const float*)d_in[0];
    const int*   ei    = (const int*)d_in[1];     // int32
    const int*   batch = (const int*)d_in[2];     // int32
    const float* W0    = (const float*)d_in[3];
    const float* g0    = (const float*)d_in[5];
    const float* be0   = (const float*)d_in[6];
    const float* W1    = (const float*)d_in[7];
    const float* g1    = (const float*)d_in[9];
    const float* be1   = (const float*)d_in[10];
    const float* Wfc   = (const float*)d_in[11];
    const float* bfc   = (const float*)d_in[12];
    float*       out   = (float*)d_out;

    int N = in_sizes[0] / HD;        // 100000
    int E = in_sizes[1] / 2;         // 1600000
    int O = out_size / NG;           // 32

    // Side stream + events for CSR-build / GEMM1 overlap (created once, reused;
    // no device memory involved, graph-capturable fork/join pattern).
    static cudaStream_t s2 = 0;
    static cudaEvent_t evFork = 0, evJoin = 0;
    if (s2 == 0) {
        cudaStreamCreateWithFlags(&s2, cudaStreamNonBlocking);
        cudaEventCreateWithFlags(&evFork, cudaEventDisableTiming);
        cudaEventCreateWithFlags(&evJoin, cudaEventDisableTiming);
    }

    cudaStream_t st = 0;
    int gemm_grid = (N + 127) / 128;
    int agg_grid  = 4096;

    // ---- fork: CSR build on s2, GEMM1 on st ----
    cudaEventRecord(evFork, st);
    cudaStreamWaitEvent(s2, evFork, 0);

    zero_kernel<<<(N + 255) / 256, 256, 0, s2>>>(N);
    deg_kernel <<<(E + 255) / 256, 256, 0, s2>>>(ei, E);
    scan_kernel<<<1, 1024, 0, s2>>>(N);
    fill_kernel<<<(E + 255) / 256, 256, 0, s2>>>(ei, E);
    cudaEventRecord(evJoin, s2);

    gemm_kernel<false><<<gemm_grid, 256, 0, st>>>(x, W0, N);

    // ---- join, then the serial chain ----
    cudaStreamWaitEvent(st, evJoin, 0);

    aggregate_kernel<0><<<agg_grid, 256, 0, st>>>(N);
    finalize_kernel<0><<<1, 128, 0, st>>>(g0, be0, N);

    gemm_kernel<true> <<<gemm_grid, 256, 0, st>>>(x /*unused*/, W1, N);
    aggregate_kernel<1><<<agg_grid, 256, 0, st>>>(N);
    finalize_kernel<1><<<1, 128, 0, st>>>(g1, be1, N);

    pool_kernel<<<512, 128, 0, st>>>(batch, N);
    fc_kernel  <<<(NG * O + 255) / 256, 256, 0, st>>>(Wfc, bfc, out, O);
}

// round 16
// speedup vs baseline: 1.5918x; 1.0141x over previous
#include <cuda_runtime.h>
#include <cuda_bf16.h>

// Problem constants (shapes fixed by the dataset; runtime values read from in_sizes)
#define MAXN 100000
#define MAXE 1600000
#define HD   128           // hidden dim (= input dim)
#define NG   64            // number of graphs
#define BN_EPS 1e-5f

// edge_index / batch are int32 on device (JAX x64-disabled demotes jnp.int64).
//
// Persistent-state zeroing invariant: every accumulator buffer is zero at entry
// (module-load zero-init on first call; each call re-zeros what it consumed
// before it returns: scan re-zeros d_cntint, finalize re-zeros d_sum/d_sq,
// tail_kernel re-zeros d_pooled/d_cnt). Deterministic across graph replays.

// ---------------- scratch (static __device__ globals; no allocation) ----------------
__device__ __align__(256) float d_dinv[MAXN];              // rsqrt(in_deg + 1)
__device__ __align__(256) int   d_cntint[MAXN];            // in-degree counts
__device__ __align__(256) int   d_rowptr[MAXN + 1];        // CSR row pointers (by dst)
__device__ __align__(256) int   d_cursor[MAXN];            // fill cursors
__device__ __align__(256) int   d_col[MAXE];               // CSR column = src node
__device__ __align__(256) float d_h   [(size_t)MAXN * HD]; // transformed features
__device__ __align__(256) float d_agg [(size_t)MAXN * HD]; // aggregated features
__device__ __align__(256) float d_sum [2][HD];
__device__ __align__(256) float d_sq  [2][HD];
__device__ __align__(256) float d_aff_a[2][HD];            // BN scale : g * rsqrt(var+eps)
__device__ __align__(256) float d_aff_c[2][HD];            // BN shift : be - mu * scale
__device__ __align__(256) float d_pooled[NG * HD];
__device__ __align__(256) float d_cnt  [NG];

// ---------------- packed f32x2 helpers ----------------
__device__ __forceinline__ unsigned long long pack2(float lo, float hi) {
    unsigned long long r;
    asm("mov.b64 %0, {%1,%2};" : "=l"(r) : "f"(lo), "f"(hi));
    return r;
}
__device__ __forceinline__ void unpack2(unsigned long long v, float& lo, float& hi) {
    asm("mov.b64 {%0,%1}, %2;" : "=f"(lo), "=f"(hi) : "l"(v));
}
__device__ __forceinline__ unsigned long long ffma2(unsigned long long a,
                                                    unsigned long long b,
                                                    unsigned long long c) {
    unsigned long long r;
    asm("fma.rn.f32x2 %0, %1, %2, %3;" : "=l"(r) : "l"(a), "l"(b), "l"(c));
    return r;
}

// ---------------- in-degree counting (by dst); d_cntint zeroed by prev call --------
__global__ void deg_kernel(const int* __restrict__ ei, int E) {
    int e = blockIdx.x * blockDim.x + threadIdx.x;
    if (e < E) atomicAdd(&d_cntint[ei[E + e]], 1);
}

// ---------------- single-block scan -> rowptr, cursor, dinv; re-zeros d_cntint -----
__global__ __launch_bounds__(1024) void scan_kernel(int N) {
    __shared__ int partial[1024];
    int t = threadIdx.x;
    int C = (N + 1023) / 1024;
    int lo = t * C, hi = min(lo + C, N);
    int s = 0;
    for (int j = lo; j < hi; j++) s += d_cntint[j];
    partial[t] = s;
    __syncthreads();
    for (int off = 1; off < 1024; off <<= 1) {
        int v = (t >= off) ? partial[t - off] : 0;
        __syncthreads();
        partial[t] += v;
        __syncthreads();
    }
    int run = (t == 0) ? 0 : partial[t - 1];
    for (int j = lo; j < hi; j++) {
        int c = d_cntint[j];
        d_cntint[j] = 0;                        // re-zero for next call
        d_rowptr[j] = run;
        d_cursor[j] = run;
        d_dinv[j]   = rsqrtf((float)c + 1.0f);  // +1 self loop
        run += c;
    }
    if (t == 1023) d_rowptr[N] = run;
}

// ---------------- CSR fill: col[pos] = src, bucketed by dst ----------------
__global__ void fill_kernel(const int* __restrict__ ei, int E) {
    int e = blockIdx.x * blockDim.x + threadIdx.x;
    if (e >= E) return;
    int s = ei[e];
    int d = ei[E + e];
    int pos = atomicAdd(&d_cursor[d], 1);
    d_col[pos] = s;
}

// ---------------- GEMM: d_h = A @ W  (K-chunk 16, packed f32x2 FMA) ----------------
// AFF=true: A is d_agg(prev layer) with BN+ReLU applied on-the-fly to each element.
template <bool AFF>
__global__ __launch_bounds__(256) void gemm_kernel(const float* __restrict__ Aexp,
                                                   const float* __restrict__ W, int M) {
    __shared__ float As[16][128];
    __shared__ float Bs[16][128];
    const float* A = AFF ? (const float*)d_agg : Aexp;

    int t   = threadIdx.x;
    int br  = blockIdx.x;
    int rowA = t >> 1;            // 0..127  A loader row
    int part = t & 1;             // which 8-wide half of the 16-k chunk
    int kw   = t >> 4;            // 0..15   B loader k
    int nw   = (t & 15) << 3;     // 0..120  B loader col*8
    int ty = t >> 4, tx = t & 15;
    int m0 = ty * 8, n0 = tx * 8;

    unsigned long long acc2[4][8];
#pragma unroll
    for (int ip = 0; ip < 4; ip++)
#pragma unroll
        for (int j = 0; j < 8; j++) acc2[ip][j] = 0ull;

    long grow = (long)br * 128 + rowA;
    bool rvalid = grow < M;

    for (int kc = 0; kc < 128; kc += 16) {
        int ka = kc + part * 8;                     // this thread's 8-k A segment
        float4 av0 = make_float4(0.f, 0.f, 0.f, 0.f);
        float4 av1 = make_float4(0.f, 0.f, 0.f, 0.f);
        if (rvalid) {
            av0 = *(const float4*)(A + grow * 128 + ka);
            av1 = *(const float4*)(A + grow * 128 + ka + 4);
        }
        if (AFF) {
            float4 aa0 = *(const float4*)(&d_aff_a[0][ka]);
            float4 cc0 = *(const float4*)(&d_aff_c[0][ka]);
            float4 aa1 = *(const float4*)(&d_aff_a[0][ka + 4]);
            float4 cc1 = *(const float4*)(&d_aff_c[0][ka + 4]);
            av0.x = fmaxf(fmaf(av0.x, aa0.x, cc0.x), 0.f);
            av0.y = fmaxf(fmaf(av0.y, aa0.y, cc0.y), 0.f);
            av0.z = fmaxf(fmaf(av0.z, aa0.z, cc0.z), 0.f);
            av0.w = fmaxf(fmaf(av0.w, aa0.w, cc0.w), 0.f);
            av1.x = fmaxf(fmaf(av1.x, aa1.x, cc1.x), 0.f);
            av1.y = fmaxf(fmaf(av1.y, aa1.y, cc1.y), 0.f);
            av1.z = fmaxf(fmaf(av1.z, aa1.z, cc1.z), 0.f);
            av1.w = fmaxf(fmaf(av1.w, aa1.w, cc1.w), 0.f);
            if (!rvalid) {
                av0 = make_float4(0.f, 0.f, 0.f, 0.f);
                av1 = make_float4(0.f, 0.f, 0.f, 0.f);
            }
        }
        float4 bv0 = *(const float4*)(W + (long)(kc + kw) * 128 + nw);
        float4 bv1 = *(const float4*)(W + (long)(kc + kw) * 128 + nw + 4);

        __syncthreads();
        As[part * 8 + 0][rowA] = av0.x;
        As[part * 8 + 1][rowA] = av0.y;
        As[part * 8 + 2][rowA] = av0.z;
        As[part * 8 + 3][rowA] = av0.w;
        As[part * 8 + 4][rowA] = av1.x;
        As[part * 8 + 5][rowA] = av1.y;
        As[part * 8 + 6][rowA] = av1.z;
        As[part * 8 + 7][rowA] = av1.w;
        *(float4*)&Bs[kw][nw]     = bv0;
        *(float4*)&Bs[kw][nw + 4] = bv1;
        __syncthreads();

#pragma unroll
        for (int k = 0; k < 16; k++) {
            const ulonglong2* ap = (const ulonglong2*)&As[k][m0];
            ulonglong2 Alo = ap[0];
            ulonglong2 Ahi = ap[1];
            unsigned long long am2[4] = {Alo.x, Alo.y, Ahi.x, Ahi.y};

            float4 b0 = *(const float4*)&Bs[k][n0];
            float4 b1 = *(const float4*)&Bs[k][n0 + 4];
            unsigned long long bd[8];
            bd[0] = pack2(b0.x, b0.x); bd[1] = pack2(b0.y, b0.y);
            bd[2] = pack2(b0.z, b0.z); bd[3] = pack2(b0.w, b0.w);
            bd[4] = pack2(b1.x, b1.x); bd[5] = pack2(b1.y, b1.y);
            bd[6] = pack2(b1.z, b1.z); bd[7] = pack2(b1.w, b1.w);

#pragma unroll
            for (int ip = 0; ip < 4; ip++)
#pragma unroll
                for (int j = 0; j < 8; j++)
                    acc2[ip][j] = ffma2(am2[ip], bd[j], acc2[ip][j]);
        }
    }

#pragma unroll
    for (int ip = 0; ip < 4; ip++) {
        float vlo[8], vhi[8];
#pragma unroll
        for (int j = 0; j < 8; j++) unpack2(acc2[ip][j], vlo[j], vhi[j]);
        long r0 = (long)br * 128 + m0 + ip * 2;
        if (r0 < M) {
            *(float4*)(d_h + r0 * 128 + n0)     = make_float4(vlo[0], vlo[1], vlo[2], vlo[3]);
            *(float4*)(d_h + r0 * 128 + n0 + 4) = make_float4(vlo[4], vlo[5], vlo[6], vlo[7]);
        }
        if (r0 + 1 < M) {
            *(float4*)(d_h + (r0 + 1) * 128 + n0)     = make_float4(vhi[0], vhi[1], vhi[2], vhi[3]);
            *(float4*)(d_h + (r0 + 1) * 128 + n0 + 4) = make_float4(vhi[4], vhi[5], vhi[6], vhi[7]);
        }
    }
}

// ---------------- gather-aggregate + fused BN stats ----------------
template <int L>
__global__ __launch_bounds__(256) void aggregate_kernel(int N) {
    __shared__ float bsum[HD];
    __shared__ float bsq [HD];
    int t = threadIdx.x;
    if (t < HD) { bsum[t] = 0.f; bsq[t] = 0.f; }
    __syncthreads();

    int warp_id = (blockIdx.x * blockDim.x + t) >> 5;
    int lane    = t & 31;
    int nwarps  = (gridDim.x * blockDim.x) >> 5;

    float4 s4 = make_float4(0.f, 0.f, 0.f, 0.f);
    float4 q4 = make_float4(0.f, 0.f, 0.f, 0.f);

    for (int n = warp_id; n < N; n += nwarps) {
        int beg = d_rowptr[n];
        int end = d_rowptr[n + 1];
        float4 acc = make_float4(0.f, 0.f, 0.f, 0.f);

        for (int j0 = beg; j0 < end; j0 += 32) {
            int cnt = min(32, end - j0);
            int  myidx  = d_col[j0 + min(lane, cnt - 1)];          // clamped, coalesced
            float mynrm = (lane < cnt) ? d_dinv[myidx] : 0.f;      // OOB lanes weight 0

            for (int k = 0; k < cnt; k += 8) {                     // fully batched
                int si[8]; float wi[8]; float4 v[8];
#pragma unroll
                for (int u = 0; u < 8; u++) {
                    si[u] = __shfl_sync(0xffffffffu, myidx, k + u);
                    wi[u] = __shfl_sync(0xffffffffu, mynrm, k + u);
                }
#pragma unroll
                for (int u = 0; u < 8; u++)
                    v[u] = *(const float4*)(d_h + (long)si[u] * 128 + lane * 4);
#pragma unroll
                for (int u = 0; u < 8; u++) {
                    acc.x = fmaf(wi[u], v[u].x, acc.x);
                    acc.y = fmaf(wi[u], v[u].y, acc.y);
                    acc.z = fmaf(wi[u], v[u].z, acc.z);
                    acc.w = fmaf(wi[u], v[u].w, acc.w);
                }
            }
        }

        float di = d_dinv[n];
        float4 hv = *(const float4*)(d_h + (long)n * 128 + lane * 4);
        float4 o;
        o.x = di * (acc.x + di * hv.x);
        o.y = di * (acc.y + di * hv.y);
        o.z = di * (acc.z + di * hv.z);
        o.w = di * (acc.w + di * hv.w);
        *(float4*)(d_agg + (long)n * 128 + lane * 4) = o;

        s4.x += o.x; s4.y += o.y; s4.z += o.z; s4.w += o.w;
        q4.x = fmaf(o.x, o.x, q4.x);
        q4.y = fmaf(o.y, o.y, q4.y);
        q4.z = fmaf(o.z, o.z, q4.z);
        q4.w = fmaf(o.w, o.w, q4.w);
    }

    int c0 = lane * 4;
    atomicAdd(&bsum[c0 + 0], s4.x); atomicAdd(&bsq[c0 + 0], q4.x);
    atomicAdd(&bsum[c0 + 1], s4.y); atomicAdd(&bsq[c0 + 1], q4.y);
    atomicAdd(&bsum[c0 + 2], s4.z); atomicAdd(&bsq[c0 + 2], q4.z);
    atomicAdd(&bsum[c0 + 3], s4.w); atomicAdd(&bsq[c0 + 3], q4.w);
    __syncthreads();
    if (t < HD) {
        atomicAdd(&d_sum[L][t], bsum[t]);
        atomicAdd(&d_sq [L][t], bsq [t]);
    }
}

// ---------------- finalize: BN affine from stats; re-zeros d_sum/d_sq ---------------
template <int L>
__global__ void finalize_kernel(const float* __restrict__ g, const float* __restrict__ be,
                                int N) {
    int c = threadIdx.x;
    float invN = 1.0f / (float)N;
    float mu  = d_sum[L][c] * invN;
    float var = d_sq[L][c] * invN - mu * mu;
    d_sum[L][c] = 0.f;                          // re-zero for next call
    d_sq [L][c] = 0.f;
    float a = g[c] * rsqrtf(var + BN_EPS);
    d_aff_a[L][c] = a;
    d_aff_c[L][c] = be[c] - mu * a;
}

// ---------------- pooling: 4-row load batching ahead of branchy accumulation --------
__global__ void pool_kernel(const int* __restrict__ batch, int N) {
    int c = threadIdx.x;
    int B = gridDim.x;
    int chunk = (N + B - 1) / B;
    int r0 = blockIdx.x * chunk;
    int r1 = min(r0 + chunk, N);
    if (r0 >= r1) return;
    float a  = d_aff_a[1][c];
    float cc = d_aff_c[1][c];
    int curg = batch[r0];
    float acc = 0.f, cnt = 0.f;
    for (int r = r0; r < r1; r += 4) {
        int m = min(4, r1 - r);
        int   gg[4];
        float vv[4];
#pragma unroll
        for (int u = 0; u < 4; u++) {
            int rr = (u < m) ? (r + u) : (r1 - 1);
            gg[u] = batch[rr];                              // broadcast across block
            vv[u] = d_agg[(long)rr * 128 + c];              // independent LDGs
        }
#pragma unroll
        for (int u = 0; u < 4; u++) {
            if (u < m) {
                if (gg[u] != curg) {
                    atomicAdd(&d_pooled[curg * HD + c], acc);
                    if (c == 0) atomicAdd(&d_cnt[curg], cnt);
                    acc = 0.f; cnt = 0.f; curg = gg[u];
                }
                acc += fmaxf(fmaf(vv[u], a, cc), 0.f);
                cnt += 1.f;
            }
        }
    }
    atomicAdd(&d_pooled[curg * HD + c], acc);
    if (c == 0) atomicAdd(&d_cnt[curg], cnt);
}

// ---------------- final FC: out[g][o] = (pooled[g]/cnt[g]) @ Wfc + bfc -------------
__global__ void fc_kernel(const float* __restrict__ Wfc, const float* __restrict__ bfc,
                          float* __restrict__ out, int O) {
    int t = blockIdx.x * blockDim.x + threadIdx.x;
    int g = t / O;
    int o = t % O;
    if (g >= NG) return;
    float inv = 1.0f / fmaxf(d_cnt[g], 1.0f);
    float s = bfc[o];
#pragma unroll 8
    for (int c = 0; c < HD; c++)
        s = fmaf(d_pooled[g * HD + c] * inv, Wfc[c * O + o], s);
    out[g * O + o] = s;
}

// ---------------- tail cleanup: re-zero d_pooled / d_cnt for the next call ----------
__global__ void tail_kernel() {
    int t = threadIdx.x;
    for (int j = t; j < NG * HD; j += blockDim.x) d_pooled[j] = 0.f;
    if (t < NG) d_cnt[t] = 0.f;
}

// =====================================================================================
extern "C" void kernel_launch(void* const* d_in, const int* in_sizes, int n_in,
                              void* d_out, int out_size) {
    const float* x     = (const float*)d_in[0];
    const int*   ei    = (const int*)d_in[1];     // int32
    const int*   batch = (const int*)d_in[2];     // int32
    const float* W0    = (const float*)d_in[3];
    const float* g0    = (const float*)d_in[5];
    const float* be0   = (const float*)d_in[6];
    const float* W1    = (const float*)d_in[7];
    const float* g1    = (const float*)d_in[9];
    const float* be1   = (const float*)d_in[10];
    const float* Wfc   = (const float*)d_in[11];
    const float* bfc   = (const float*)d_in[12];
    float*       out   = (float*)d_out;

    int N = in_sizes[0] / HD;        // 100000
    int E = in_sizes[1] / 2;         // 1600000
    int O = out_size / NG;           // 32

    static cudaStream_t s2 = 0;
    static cudaEvent_t evFork = 0, evJoin = 0;
    if (s2 == 0) {
        cudaStreamCreateWithFlags(&s2, cudaStreamNonBlocking);
        cudaEventCreateWithFlags(&evFork, cudaEventDisableTiming);
        cudaEventCreateWithFlags(&evJoin, cudaEventDisableTiming);
    }

    cudaStream_t st = 0;
    int gemm_grid = (N + 127) / 128;
    int agg_grid  = 4096;

    // ---- fork: CSR build on s2, GEMM1 on st ----
    cudaEventRecord(evFork, st);
    cudaStreamWaitEvent(s2, evFork, 0);

    deg_kernel <<<(E + 255) / 256, 256, 0, s2>>>(ei, E);
    scan_kernel<<<1, 1024, 0, s2>>>(N);
    fill_kernel<<<(E + 255) / 256, 256, 0, s2>>>(ei, E);
    cudaEventRecord(evJoin, s2);

    gemm_kernel<false><<<gemm_grid, 256, 0, st>>>(x, W0, N);

    // ---- join, then the serial chain ----
    cudaStreamWaitEvent(st, evJoin, 0);

    aggregate_kernel<0><<<agg_grid, 256, 0, st>>>(N);
    finalize_kernel<0><<<1, 128, 0, st>>>(g0, be0, N);

    gemm_kernel<true> <<<gemm_grid, 256, 0, st>>>(x /*unused*/, W1, N);
    aggregate_kernel<1><<<agg_grid, 256, 0, st>>>(N);
    finalize_kernel<1><<<1, 128, 0, st>>>(g1, be1, N);

    pool_kernel<<<512, 128, 0, st>>>(batch, N);
    fc_kernel  <<<(NG * O + 255) / 256, 256, 0, st>>>(Wfc, bfc, out, O);
    tail_kernel<<<1, 256, 0, st>>>();
}